// round 15
// baseline (speedup 1.0000x reference)
#include <cuda_runtime.h>
#include <cstdint>

// Problem constants (fixed by dataset): B=1, N=4096, C=8, H=W=128, K=8
#define MAXN 8192
constexpr float RADIUS = 0.05f;
constexpr int H = 128, W = 128, C = 8, K = 8;
constexpr int TILE = 8;             // 8x8 pixel tiles
constexpr int TX = W / TILE;        // 16
constexpr int TY = H / TILE;        // 16
constexpr int NTILES = TX * TY;     // 256 tiles
constexpr int NBLK = NTILES / 2;    // 128 CTAs (single wave on 148 SMs)
constexpr int PIX2 = 2 * TILE * TILE;  // 128 pixels per CTA
constexpr int TPB = 1024;           // 32 warps/CTA -> full latency hiding at 1 CTA/SM
constexpr int CAPT = 256;           // per-tile candidate cap (mean ~52, max ~90)
constexpr int PIXCAP = 36;          // per-pixel hit cap (mean ~8, Poisson tail ~1e-13)

// smem layout (45056 B static + counters):
//   [    0,  8192)  s_cand  float4[2][256]   (dead after phase 2)
//   [ 8192, 26624)  s_hz    float[128][36]
//   [26624, 45056)  s_hi    int  [128][36]
//   [    0,  4096)  s_wk    float[128][8]  ── aliases s_cand in phase 3
//   [ 4096,  8192)  s_ik    int  [128][8]  ──
constexpr int RAWSZ = 45056;

__global__ void __launch_bounds__(TPB, 1)
render_kernel(const float* __restrict__ pts,
              const float* __restrict__ feat,
              float* __restrict__ out, int n) {
    __shared__ __align__(16) unsigned char raw[RAWSZ];
    float4* s_cand = (float4*)raw;
    float*  s_hz   = (float*)(raw + 8192);
    int*    s_hi   = (int*)  (raw + 26624);
    float*  s_wk   = (float*)raw;            // alias (phase 3)
    int*    s_ik   = (int*)  (raw + 4096);   // alias (phase 3)
    __shared__ int s_cnt[2];
    __shared__ int s_pixcnt[PIX2];

    const int tile0 = blockIdx.x * 2;        // two tiles in the same row (TX even)
    const int tx0 = tile0 & (TX - 1);
    const int ty  = tile0 >> 4;
    const int tid = threadIdx.x;

    if (tid < PIX2) s_pixcnt[tid] = 0;
    if (tid < 2)    s_cnt[tid] = 0;
    __syncthreads();

    // ---- bboxes over pixel centers, expanded by splat radius + eps (NDC) ----
    const float EPS = 1e-5f;
    // union bbox of both tiles (16x8 pixels)
    const float ux0 = ((float)(tx0 * TILE)      + 0.5f) * (2.0f / W) - 1.0f - RADIUS - EPS;
    const float ux1 = ((float)(tx0 * TILE + 15) + 0.5f) * (2.0f / W) - 1.0f + RADIUS + EPS;
    const float uy0 = ((float)(ty * TILE)       + 0.5f) * (2.0f / H) - 1.0f - RADIUS - EPS;
    const float uy1 = ((float)(ty * TILE + 7)   + 0.5f) * (2.0f / H) - 1.0f + RADIUS + EPS;
    // per-tile x bounds (y is shared)
    float tbx0[2], tbx1[2];
    #pragma unroll
    for (int hf = 0; hf < 2; hf++) {
        tbx0[hf] = ((float)((tx0 + hf) * TILE)     + 0.5f) * (2.0f / W) - 1.0f - RADIUS - EPS;
        tbx1[hf] = ((float)((tx0 + hf) * TILE + 7) + 0.5f) * (2.0f / W) - 1.0f + RADIUS + EPS;
    }

    // ---- Phase 1: cull all points vs UNION bbox (division-free, coalesced
    //      scalar loads), classify survivors into the 2 per-tile lists -------
    #pragma unroll
    for (int it = 0; it < MAXN / TPB; it++) {
        int i = it * TPB + tid;
        if (i < n) {
            float x = pts[3 * i + 0];
            float y = pts[3 * i + 1];
            float z = pts[3 * i + 2];
            // z>0: x/z >= ux0  <=>  x >= ux0*z  (conservative; exact test later)
            bool hit = (z > 0.0f) &&
                       (x >= ux0 * z) && (x <= ux1 * z) &&
                       (y >= uy0 * z) && (y <= uy1 * z);
            if (hit) {
                float px = x / z;          // exact IEEE, matches reference
                float py = y / z;
                float4 rec = make_float4(px, py, z, __int_as_float(i));
                #pragma unroll
                for (int t = 0; t < 2; t++) {
                    if (px >= tbx0[t] && px <= tbx1[t]) {
                        int slot = atomicAdd(&s_cnt[t], 1);
                        if (slot < CAPT) s_cand[t * CAPT + slot] = rec;
                    }
                }
            }
        }
    }
    __syncthreads();

    // ---- Phase 2: 8 lanes per pixel scan the owning tile's list ------------
    const int p  = tid >> 3;               // pixel 0..127
    const int s8 = tid & 7;                // lane 0..7
    const int t  = p >> 6;                 // tile half 0..1
    const int lp = p & 63;
    const int lx = lp & (TILE - 1);
    const int ly = lp >> 3;
    const float gx = ((float)((tx0 + t) * TILE + lx) + 0.5f) * (2.0f / W) - 1.0f;
    const float gy = ((float)(ty * TILE + ly)        + 0.5f) * (2.0f / H) - 1.0f;
    const float r2 = RADIUS * RADIUS;
    {
        const int cnt = min(s_cnt[t], CAPT);
        for (int j = s8; j < cnt; j += 8) {
            float4 cd = s_cand[t * CAPT + j];
            float dx = gx - cd.x;
            float dy = gy - cd.y;
            float d2 = dx * dx + dy * dy;
            if (d2 < r2) {                 // exact hit test (matches reference)
                int slot = atomicAdd(&s_pixcnt[p], 1);
                if (slot < PIXCAP) {
                    s_hz[p * PIXCAP + slot] = cd.z;
                    s_hi[p * PIXCAP + slot] = __float_as_int(cd.w);
                }
            }
        }
    }
    __syncthreads();   // also protects the s_cand -> s_wk/s_ik aliasing below

    // ---- Phase 3a: one thread per pixel: top-8 by z, weights -> smem -------
    if (tid < PIX2) {
        const int pp = tid;
        const int hc = min(s_pixcnt[pp], PIXCAP);
        const int tt = pp >> 6;
        const int llx = pp & (TILE - 1);
        const int lly = (pp & 63) >> 3;
        const float pgx = ((float)((tx0 + tt) * TILE + llx) + 0.5f) * (2.0f / W) - 1.0f;
        const float pgy = ((float)(ty * TILE + lly)         + 0.5f) * (2.0f / H) - 1.0f;

        float lz[K];
        int   li[K];
        #pragma unroll
        for (int k = 0; k < K; k++) { lz[k] = 3.0e38f; li[k] = 0; }
        for (int j = 0; j < hc; j++) {
            float z = s_hz[pp * PIXCAP + j];
            // distinct depths -> top-K set is order-independent (matches top_k)
            if (z < lz[K - 1]) {
                lz[K - 1] = z; li[K - 1] = s_hi[pp * PIXCAP + j];
                #pragma unroll
                for (int k = K - 1; k > 0; k--) {
                    if (lz[k] < lz[k - 1]) {
                        float t0 = lz[k]; lz[k] = lz[k - 1]; lz[k - 1] = t0;
                        int   t2 = li[k]; li[k] = li[k - 1]; li[k - 1] = t2;
                    }
                }
            }
        }

        // reload winners' x,y (8 independent pairs, one latency round);
        // px = x/z with the SAME z bits -> identical projection as phase 1
        float pxk[K], pyk[K];
        #pragma unroll
        for (int k = 0; k < K; k++) {
            int id = (lz[k] < 1.0e38f) ? li[k] : 0;
            float x = __ldg(&pts[3 * id + 0]);
            float y = __ldg(&pts[3 * id + 1]);
            pxk[k] = x / lz[k];            // invalid: x/3e38 ~ 0, weight forced 0
            pyk[k] = y / lz[k];
        }

        float T = 1.0f;
        const float inv_r2 = 1.0f / r2;
        #pragma unroll
        for (int k = 0; k < K; k++) {
            bool valid = lz[k] < 1.0e38f;
            float dx = pgx - pxk[k];
            float dy = pgy - pyk[k];
            float d2 = dx * dx + dy * dy;
            float a = fminf(fmaxf(1.0f - d2 * inv_r2, 0.0f), 1.0f);
            a = valid ? a : 0.0f;
            s_wk[pp * K + k] = a * T;
            s_ik[pp * K + k] = valid ? li[k] : 0;
            T *= (1.0f - a);
        }
    }
    __syncthreads();

    // ---- Phase 3b: 2 threads per pixel gather features (one parallel round)
    if (tid < 2 * PIX2) {
        const int pp = tid >> 1;           // pixel 0..127
        const int hf = tid & 1;            // channel half
        float4 F[K];
        float  wks[K];
        #pragma unroll
        for (int k = 0; k < K; k++) {
            wks[k] = s_wk[pp * K + k];
            int id = s_ik[pp * K + k];
            F[k] = __ldg(&((const float4*)(feat + (size_t)id * C))[hf]);
        }
        float a0 = 0.0f, a1 = 0.0f, a2 = 0.0f, a3 = 0.0f;
        #pragma unroll
        for (int k = 0; k < K; k++) {
            a0 += wks[k] * F[k].x;
            a1 += wks[k] * F[k].y;
            a2 += wks[k] * F[k].z;
            a3 += wks[k] * F[k].w;
        }
        const int tt = pp >> 6;
        const int pix_x = (tx0 + tt) * TILE + (pp & (TILE - 1));
        const int pix_y = ty * TILE + ((pp & 63) >> 3);
        float4* o = (float4*)(out + (size_t)(pix_y * W + pix_x) * C);
        o[hf] = make_float4(a0, a1, a2, a3);
    }
}

extern "C" void kernel_launch(void* const* d_in, const int* in_sizes, int n_in,
                              void* d_out, int out_size) {
    const float* pts  = (const float*)d_in[0];   // [B,N,3] f32
    const float* feat = (const float*)d_in[1];   // [B,N,C] f32
    float* out = (float*)d_out;                  // [B,H,W,C] f32
    int n = in_sizes[0] / 3;                     // B=1 -> N
    if (n > MAXN) n = MAXN;

    render_kernel<<<NBLK, TPB>>>(pts, feat, out, n);
}

// round 16
// speedup vs baseline: 1.4521x; 1.4521x over previous
#include <cuda_runtime.h>
#include <cstdint>

// Problem constants (fixed by dataset): B=1, N=4096, C=8, H=W=128, K=8
#define MAXN 8192
constexpr float RADIUS = 0.05f;
constexpr int H = 128, W = 128, C = 8, K = 8;
constexpr int TILE = 8;             // 8x8 pixel tiles
constexpr int TX = W / TILE;        // 16
constexpr int TY = H / TILE;        // 16
constexpr int NTILES = TX * TY;     // 256 CTAs
constexpr int PIX = TILE * TILE;    // 64 pixels per tile
constexpr int SPLIT = 8;            // threads per pixel in scan phase
constexpr int TPB = PIX * SPLIT;    // 512 threads per CTA
constexpr int QCAP = 192;           // per-quadrant cap (mean ~27)
constexpr int PIXCAP = 40;          // per-pixel hit cap (mean ~8)

// smem: quadrant lists 4*192*16 = 12288 B; hit lists 64*40*12 = 30720 B -> 43008 B
constexpr int RAWSZ = 4 * QCAP * 16 + PIX * PIXCAP * 12;

__global__ void __launch_bounds__(TPB)
render_kernel(const float* __restrict__ pts,
              const float* __restrict__ feat,
              float* __restrict__ out, int n) {
    __shared__ __align__(16) unsigned char raw[RAWSZ];
    float4* s_quad = (float4*)raw;                                  // [4][QCAP]
    float*  s_hz   = (float*)(raw + 4 * QCAP * 16);                 // [64][40]
    float*  s_hd   = (float*)(raw + 4 * QCAP * 16 + PIX * PIXCAP * 4);
    int*    s_hi   = (int*)  (raw + 4 * QCAP * 16 + PIX * PIXCAP * 8);
    __shared__ int s_qcnt[4];
    __shared__ int s_pixcnt[PIX];

    const int tile = blockIdx.x;
    const int tx = tile & (TX - 1);
    const int ty = tile >> 4;
    const int tid = threadIdx.x;

    if (tid < PIX) s_pixcnt[tid] = 0;
    if (tid < 4)   s_qcnt[tid] = 0;
    __syncthreads();

    // ---- bboxes over pixel centers, expanded by splat radius + eps (NDC) ----
    const float EPS = 1e-5f;
    const float x0 = ((float)(tx * TILE)            + 0.5f) * (2.0f / W) - 1.0f - RADIUS - EPS;
    const float x1 = ((float)(tx * TILE + TILE - 1) + 0.5f) * (2.0f / W) - 1.0f + RADIUS + EPS;
    const float y0 = ((float)(ty * TILE)            + 0.5f) * (2.0f / H) - 1.0f - RADIUS - EPS;
    const float y1 = ((float)(ty * TILE + TILE - 1) + 0.5f) * (2.0f / H) - 1.0f + RADIUS + EPS;

    float qx0[2], qx1[2], qy0[2], qy1[2];
    #pragma unroll
    for (int hf = 0; hf < 2; hf++) {
        qx0[hf] = ((float)(tx * TILE + hf * 4)     + 0.5f) * (2.0f / W) - 1.0f - RADIUS - EPS;
        qx1[hf] = ((float)(tx * TILE + hf * 4 + 3) + 0.5f) * (2.0f / W) - 1.0f + RADIUS + EPS;
        qy0[hf] = ((float)(ty * TILE + hf * 4)     + 0.5f) * (2.0f / H) - 1.0f - RADIUS - EPS;
        qy1[hf] = ((float)(ty * TILE + hf * 4 + 3) + 0.5f) * (2.0f / H) - 1.0f + RADIUS + EPS;
    }

    // ---- Phase 1: cull all points vs tile bbox (division-free, coalesced
    //      scalar loads). #pragma unroll 1 is deliberate: it caps MLP_p1
    //      (front-batched LDG count) at ~3, avoiding the documented B300
    //      cross-CTA L1tex-queue contention spread (spr_max ~2x at high
    //      MLP_p1 with 2 CTAs/SM). TLP (32 warps/SM) hides the latency. -----
    #pragma unroll 1
    for (int it = 0; it < MAXN / TPB; it++) {
        int i = it * TPB + tid;
        if (i < n) {
            float x = pts[3 * i + 0];
            float y = pts[3 * i + 1];
            float z = pts[3 * i + 2];
            // z>0: x/z >= x0  <=>  x >= x0*z  (conservative; exact test later)
            bool hit = (z > 0.0f) &&
                       (x >= x0 * z) && (x <= x1 * z) &&
                       (y >= y0 * z) && (y <= y1 * z);
            if (hit) {
                float px = x / z;          // exact IEEE, matches reference
                float py = y / z;
                float4 rec = make_float4(px, py, z, __int_as_float(i));
                #pragma unroll
                for (int q = 0; q < 4; q++) {
                    if (px >= qx0[q & 1] && px <= qx1[q & 1] &&
                        py >= qy0[q >> 1] && py <= qy1[q >> 1]) {
                        int slot = atomicAdd(&s_qcnt[q], 1);
                        if (slot < QCAP) s_quad[q * QCAP + slot] = rec;
                    }
                }
            }
        }
    }
    __syncthreads();

    // ---- Phase 2: scan own quadrant list, push exact hits per pixel --------
    const int p = tid >> 3;                // pixel 0..63
    const int s = tid & 7;                 // sub-lane 0..7
    const int lx = p & (TILE - 1);
    const int ly = p >> 3;
    const int q  = ((ly >> 2) << 1) | (lx >> 2);
    const float gx = ((float)(tx * TILE + lx) + 0.5f) * (2.0f / W) - 1.0f;
    const float gy = ((float)(ty * TILE + ly) + 0.5f) * (2.0f / H) - 1.0f;
    const float r2 = RADIUS * RADIUS;
    {
        const int qc = min(s_qcnt[q], QCAP);
        for (int j = s; j < qc; j += SPLIT) {
            float4 cd = s_quad[q * QCAP + j];
            float dx = gx - cd.x;
            float dy = gy - cd.y;
            float d2 = dx * dx + dy * dy;
            if (d2 < r2) {                 // exact hit test (matches reference)
                int slot = atomicAdd(&s_pixcnt[p], 1);
                if (slot < PIXCAP) {
                    int o = p * PIXCAP + slot;
                    s_hz[o] = cd.z;
                    s_hd[o] = d2;
                    s_hi[o] = __float_as_int(cd.w);
                }
            }
        }
    }
    __syncthreads();

    // ---- Phase 3: per-pixel top-8 by depth + composite + store (tid<64) ----
    if (tid < PIX) {
        const int pp = tid;
        const int pix_x = tx * TILE + (pp & (TILE - 1));
        const int pix_y = ty * TILE + (pp >> 3);
        const int hc = min(s_pixcnt[pp], PIXCAP);

        float lz[K], ldd[K];
        int   li[K];
        #pragma unroll
        for (int k = 0; k < K; k++) { lz[k] = 3.0e38f; ldd[k] = 0.0f; li[k] = 0; }

        for (int j = 0; j < hc; j++) {
            int o = pp * PIXCAP + j;
            float z = s_hz[o];
            // distinct depths -> top-K set is order-independent (matches top_k)
            if (z < lz[K - 1]) {
                lz[K - 1] = z; ldd[K - 1] = s_hd[o]; li[K - 1] = s_hi[o];
                #pragma unroll
                for (int k = K - 1; k > 0; k--) {
                    if (lz[k] < lz[k - 1]) {
                        float t0 = lz[k];  lz[k]  = lz[k - 1];  lz[k - 1]  = t0;
                        float t1 = ldd[k]; ldd[k] = ldd[k - 1]; ldd[k - 1] = t1;
                        int   t2 = li[k];  li[k]  = li[k - 1];  li[k - 1]  = t2;
                    }
                }
            }
        }

        // front-to-back weights, then batched feature gather (MLP 4 per round)
        float wk[K];
        int   idk[K];
        float T = 1.0f;
        const float inv_r2 = 1.0f / r2;
        #pragma unroll
        for (int k = 0; k < K; k++) {
            bool valid = lz[k] < 1.0e38f;
            float a = 1.0f - ldd[k] * inv_r2;
            a = fminf(fmaxf(a, 0.0f), 1.0f);
            a = valid ? a : 0.0f;
            wk[k]  = a * T;
            idk[k] = valid ? li[k] : 0;
            T *= (1.0f - a);
        }

        float acc[C];
        #pragma unroll
        for (int c2 = 0; c2 < C; c2++) acc[c2] = 0.0f;
        #pragma unroll
        for (int half = 0; half < 2; half++) {
            float4 F0[4], F1[4];
            #pragma unroll
            for (int k = 0; k < 4; k++) {
                const float4* f = (const float4*)(feat + (size_t)idk[half * 4 + k] * C);
                F0[k] = __ldg(&f[0]);
                F1[k] = __ldg(&f[1]);
            }
            #pragma unroll
            for (int k = 0; k < 4; k++) {
                float w = wk[half * 4 + k];
                acc[0] += w * F0[k].x; acc[1] += w * F0[k].y;
                acc[2] += w * F0[k].z; acc[3] += w * F0[k].w;
                acc[4] += w * F1[k].x; acc[5] += w * F1[k].y;
                acc[6] += w * F1[k].z; acc[7] += w * F1[k].w;
            }
        }

        float4* o = (float4*)(out + (size_t)(pix_y * W + pix_x) * C);
        o[0] = make_float4(acc[0], acc[1], acc[2], acc[3]);
        o[1] = make_float4(acc[4], acc[5], acc[6], acc[7]);
    }
}

extern "C" void kernel_launch(void* const* d_in, const int* in_sizes, int n_in,
                              void* d_out, int out_size) {
    const float* pts  = (const float*)d_in[0];   // [B,N,3] f32
    const float* feat = (const float*)d_in[1];   // [B,N,C] f32
    float* out = (float*)d_out;                  // [B,H,W,C] f32
    int n = in_sizes[0] / 3;                     // B=1 -> N
    if (n > MAXN) n = MAXN;

    render_kernel<<<NTILES, TPB>>>(pts, feat, out, n);
}